// round 16
// baseline (speedup 1.0000x reference)
#include <cuda_runtime.h>
#include <cuda_fp16.h>
#include <cstdint>

#define NMAX 200000
#define GMAX 64

// ---------------- scratch (device-code references ONLY; self-cleaning) --------
__device__ __align__(16) uint4 g_h1h[NMAX];   // 8 x fp16 (6 used): UNscaled x@W1
__device__ __align__(16) uint4 g_u1h[NMAX];   // 8 x fp16: dis*h1 (message)
__device__ __align__(16) uint4 g_a1h[NMAX];   // fp16 accumulator, init = self term
__device__ __align__(16) uint4 g_u2h[NMAX];   // 8 x fp16: dis*relu(layer1)
__device__ __align__(16) uint4 g_a2h[NMAX];   // fp16 accumulator, init = self term
__device__ int      g_deg[NMAX];              // zeroed in phase 2 after use
__device__ float    g_dis[NMAX];
__device__ float    g_pool[GMAX * 6];         // zeroed in phase 7 after use
__device__ float    g_cnt[GMAX];              // zeroed in phase 7 after use
__device__ volatile unsigned g_bar_arrive;    // reset by barrier protocol / phase 7
__device__ volatile unsigned g_bar_gen;       // reset in phase 7

// ---------------- helpers ------------------------------------------------------
__device__ __forceinline__ void red2f(float* p, float a, float b) {
    asm volatile("red.global.add.v2.f32 [%0], {%1,%2};"
                 :: "l"(p), "f"(a), "f"(b) : "memory");
}
__device__ __forceinline__ void red16h(uint4* p, uint4 m) {
    asm volatile("red.global.add.noftz.v4.f16x2 [%0], {%1,%2,%3,%4};"
                 :: "l"(p), "r"(m.x), "r"(m.y), "r"(m.z), "r"(m.w) : "memory");
}
__device__ __forceinline__ uint32_t pack2(float a, float b) {
    __half2 h = __floats2half2_rn(a, b);
    return *(uint32_t*)&h;
}
__device__ __forceinline__ float2 up2(uint32_t w) {
    return __half22float2(*(__half2*)&w);
}

// Software grid barrier. Safe: grid sized by the occupancy API so all blocks
// are co-resident. Generation counter avoids ABA across the 6 uses per call.
__device__ __forceinline__ void gridBarrier() {
    __threadfence();
    __syncthreads();
    if (threadIdx.x == 0) {
        unsigned gen = g_bar_gen;
        unsigned prev = atomicAdd((unsigned*)&g_bar_arrive, 1u);
        if (prev == gridDim.x - 1) {
            g_bar_arrive = 0;
            __threadfence();
            g_bar_gen = gen + 1;
        } else {
            while (g_bar_gen == gen) __nanosleep(64);
        }
        __threadfence();
    }
    __syncthreads();
}

// ---------------- the whole model as one persistent kernel -----------------------
__global__ void __launch_bounds__(256) kAll(const float* __restrict__ x,
                                            const int* __restrict__ ei,
                                            const int* __restrict__ batch,
                                            const float* __restrict__ W1,
                                            const float* __restrict__ b1,
                                            const float* __restrict__ W2,
                                            const float* __restrict__ b2,
                                            float* __restrict__ out,
                                            int N, int E, int G) {
    __shared__ float sx[32 * 132];
    __shared__ float sW[768];
    __shared__ float sb1s[6];
    const int tid  = threadIdx.x;
    const int nth  = gridDim.x * 256;
    const int gtid = blockIdx.x * 256 + tid;
    const int* col = ei + E;

    if (tid < 6) sb1s[tid] = b1[tid];

    // ================= Phase 1: role-split deg count + H1 matmul ================
    bool degRole = (gridDim.x > 1) && (blockIdx.x & 1);
    if (degRole) {
        int nDeg = gridDim.x >> 1;
        int db = blockIdx.x >> 1;
        if ((E & 3) == 0) {
            int ds = nDeg * 1024;
            for (int e = (db * 256 + tid) * 4; e < E; e += ds) {
                int4 a = *(const int4*)(col + e);
                atomicAdd(&g_deg[a.x], 1); atomicAdd(&g_deg[a.y], 1);
                atomicAdd(&g_deg[a.z], 1); atomicAdd(&g_deg[a.w], 1);
            }
        } else {
            int ds = nDeg * 256;
            for (int e = db * 256 + tid; e < E; e += ds)
                atomicAdd(&g_deg[__ldg(col + e)], 1);
        }
    } else {
        if (gridDim.x == 1) {   // degenerate: do deg serially first
            for (int e = tid; e < E; e += 256) atomicAdd(&g_deg[__ldg(col + e)], 1);
        }
        for (int i = tid; i < 768; i += 256) sW[i] = W1[i];
        int nH = (gridDim.x + 1) >> 1;
        int hb = blockIdx.x >> 1;
        int HB = (N + 31) >> 5;
        for (int q = hb; q < HB; q += nH) {
            __syncthreads();
            int base = q * 32;
#pragma unroll
            for (int it = 0; it < 4; it++) {
                int f = tid + 256 * it;
                int node = f >> 5, c = f & 31;
                int gn = base + node;
                float4 v = make_float4(0.f, 0.f, 0.f, 0.f);
                if (gn < N) v = __ldcs((const float4*)(x + (size_t)gn * 128 + c * 4));
                *(float4*)&sx[node * 132 + c * 4] = v;
            }
            __syncthreads();
            int node = tid >> 3, sub = tid & 7;   // 8 threads per node
            int gn = base + node;
            float a0 = 0.f, a1 = 0.f, a2 = 0.f, a3 = 0.f, a4 = 0.f, a5 = 0.f;
#pragma unroll
            for (int c = sub; c < 32; c += 8) {
                float4 xv = *(const float4*)&sx[node * 132 + c * 4];
                const float4* wp = (const float4*)&sW[c * 24];
                float4 w0 = wp[0], w1 = wp[1], w2 = wp[2], w3 = wp[3], w4 = wp[4], w5 = wp[5];
                a0 += xv.x * w0.x + xv.y * w1.z + xv.z * w3.x + xv.w * w4.z;
                a1 += xv.x * w0.y + xv.y * w1.w + xv.z * w3.y + xv.w * w4.w;
                a2 += xv.x * w0.z + xv.y * w2.x + xv.z * w3.z + xv.w * w5.x;
                a3 += xv.x * w0.w + xv.y * w2.y + xv.z * w3.w + xv.w * w5.y;
                a4 += xv.x * w1.x + xv.y * w2.z + xv.z * w4.x + xv.w * w5.z;
                a5 += xv.x * w1.y + xv.y * w2.w + xv.z * w4.y + xv.w * w5.w;
            }
#pragma unroll
            for (int o = 4; o; o >>= 1) {
                a0 += __shfl_xor_sync(0xffffffffu, a0, o, 8);
                a1 += __shfl_xor_sync(0xffffffffu, a1, o, 8);
                a2 += __shfl_xor_sync(0xffffffffu, a2, o, 8);
                a3 += __shfl_xor_sync(0xffffffffu, a3, o, 8);
                a4 += __shfl_xor_sync(0xffffffffu, a4, o, 8);
                a5 += __shfl_xor_sync(0xffffffffu, a5, o, 8);
            }
            if (sub == 0 && gn < N) {
                uint4 m;
                m.x = pack2(a0, a1);
                m.y = pack2(a2, a3);
                m.z = pack2(a4, a5);
                m.w = 0u;
                g_h1h[gn] = m;
            }
        }
    }
    gridBarrier();

    // ================= Phase 2: dis; u1 = dis*h1; a1 = u1; deg self-clean ========
    for (int i = gtid; i < N; i += nth) {
        float d = rsqrtf((float)(g_deg[i] + 1));
        g_deg[i] = 0;
        g_dis[i] = d;
        uint4 h = g_h1h[i];
        float2 s0 = up2(h.x), s1 = up2(h.y), s2 = up2(h.z);
        uint4 m;
        m.x = pack2(d * s0.x, d * s0.y);
        m.y = pack2(d * s1.x, d * s1.y);
        m.z = pack2(d * s2.x, d * s2.y);
        m.w = 0u;
        g_u1h[i] = m;
        g_a1h[i] = m;
    }
    gridBarrier();

    // ================= Phase 3: edge aggregation layer 1 ==========================
    if ((E & 3) == 0) {
        for (int t = gtid * 4; t < E; t += nth * 4) {
            int4 rr = *(const int4*)(ei + t);
            int4 cc = *(const int4*)(ei + E + t);
            uint4 m0 = g_u1h[rr.x];
            uint4 m1 = g_u1h[rr.y];
            uint4 m2 = g_u1h[rr.z];
            uint4 m3 = g_u1h[rr.w];
            red16h(&g_a1h[cc.x], m0);
            red16h(&g_a1h[cc.y], m1);
            red16h(&g_a1h[cc.z], m2);
            red16h(&g_a1h[cc.w], m3);
        }
    } else {
        for (int t = gtid; t < E; t += nth) {
            int r = __ldg(ei + t), c = __ldg(ei + E + t);
            uint4 m = g_u1h[r];
            red16h(&g_a1h[c], m);
        }
    }
    gridBarrier();

    // ================= Phase 4: u2 = pack(dis*relu(dis*a1 + b1)); a2 = u2 =========
    for (int i = gtid; i < N; i += nth) {
        float d = g_dis[i];
        uint4 a = g_a1h[i];
        float2 s0 = up2(a.x), s1 = up2(a.y), s2 = up2(a.z);
        float r0 = fmaxf(d * s0.x + sb1s[0], 0.f);
        float r1 = fmaxf(d * s0.y + sb1s[1], 0.f);
        float r2 = fmaxf(d * s1.x + sb1s[2], 0.f);
        float r3 = fmaxf(d * s1.y + sb1s[3], 0.f);
        float r4 = fmaxf(d * s2.x + sb1s[4], 0.f);
        float r5 = fmaxf(d * s2.y + sb1s[5], 0.f);
        uint4 w;
        w.x = pack2(d * r0, d * r1);
        w.y = pack2(d * r2, d * r3);
        w.z = pack2(d * r4, d * r5);
        w.w = 0u;
        g_u2h[i] = w;
        g_a2h[i] = w;
    }
    gridBarrier();

    // ================= Phase 5: edge aggregation layer 2 ==========================
    if ((E & 3) == 0) {
        for (int t = gtid * 4; t < E; t += nth * 4) {
            int4 rr = *(const int4*)(ei + t);
            int4 cc = *(const int4*)(ei + E + t);
            uint4 m0 = g_u2h[rr.x];
            uint4 m1 = g_u2h[rr.y];
            uint4 m2 = g_u2h[rr.z];
            uint4 m3 = g_u2h[rr.w];
            red16h(&g_a2h[cc.x], m0);
            red16h(&g_a2h[cc.y], m1);
            red16h(&g_a2h[cc.z], m2);
            red16h(&g_a2h[cc.w], m3);
        }
    } else {
        for (int t = gtid; t < E; t += nth) {
            int r = __ldg(ei + t), c = __ldg(ei + E + t);
            uint4 m = g_u2h[r];
            red16h(&g_a2h[c], m);
        }
    }
    gridBarrier();

    // ================= Phase 6: mean-pool accumulation ============================
    for (int ibase = blockIdx.x * 256; ibase < N; ibase += nth) {
        int i = ibase + tid;
        float v[6];
        float cn = 0.f;
        int g = -1;
        if (i < N) {
            g = batch[i];
            float d = g_dis[i];
            uint4 a = g_a2h[i];
            float2 s0 = up2(a.x), s1 = up2(a.y), s2 = up2(a.z);
            v[0] = d * s0.x; v[1] = d * s0.y;
            v[2] = d * s1.x; v[3] = d * s1.y;
            v[4] = d * s2.x; v[5] = d * s2.y;
            cn = 1.f;
        } else {
#pragma unroll
            for (int j = 0; j < 6; j++) v[j] = 0.f;
        }
        int g0 = __shfl_sync(0xffffffffu, g, 0);
        bool uni = __all_sync(0xffffffffu, g == g0) && (g0 >= 0);
        if (uni) {
#pragma unroll
            for (int j = 0; j < 6; j++) {
#pragma unroll
                for (int o = 16; o; o >>= 1) v[j] += __shfl_xor_sync(0xffffffffu, v[j], o);
            }
#pragma unroll
            for (int o = 16; o; o >>= 1) cn += __shfl_xor_sync(0xffffffffu, cn, o);
            if ((tid & 31) == 0) {
                float* dst = g_pool + g0 * 6;
                red2f(dst,     v[0], v[1]);
                red2f(dst + 2, v[2], v[3]);
                red2f(dst + 4, v[4], v[5]);
                atomicAdd(&g_cnt[g0], cn);
            }
        } else if (g >= 0) {
#pragma unroll
            for (int j = 0; j < 6; j++) atomicAdd(&g_pool[g * 6 + j], v[j]);
            atomicAdd(&g_cnt[g], 1.f);
        }
    }
    gridBarrier();

    // ================= Phase 7: block 0 -> log_softmax + full self-clean ==========
    if (blockIdx.x == 0) {
        __shared__ float sW2[60];
        __shared__ float sb2s[10];
        if (tid < 60) sW2[tid] = W2[tid];
        if (tid < 10) sb2s[tid] = b2[tid];
        __syncthreads();
        if (tid < G) {
            float c = fmaxf(g_cnt[tid], 1.f);
            float p[6];
#pragma unroll
            for (int k = 0; k < 6; k++) p[k] = g_pool[tid * 6 + k] / c;
            float vv[10], m = -1e30f;
#pragma unroll
            for (int j = 0; j < 10; j++) {
                float s = sb2s[j];
#pragma unroll
                for (int k = 0; k < 6; k++) s += p[k] * sW2[k * 10 + j];
                vv[j] = s;
                m = fmaxf(m, s);
            }
            float s = 0.f;
#pragma unroll
            for (int j = 0; j < 10; j++) s += expf(vv[j] - m);
            float l = m + logf(s);
#pragma unroll
            for (int j = 0; j < 10; j++) out[tid * 10 + j] = vv[j] - l;
        }
        __syncthreads();
        for (int k = tid; k < GMAX * 6; k += 256) g_pool[k] = 0.f;
        if (tid < GMAX) g_cnt[tid] = 0.f;
        if (tid == 0) { g_bar_gen = 0; g_bar_arrive = 0; }
    }
}

// ---------------- launch: one persistent, co-resident grid -------------------------
extern "C" void kernel_launch(void* const* d_in, const int* in_sizes, int n_in,
                              void* d_out, int out_size) {
    const float* x     = (const float*)d_in[0];
    const int*   ei    = (const int*)d_in[1];
    const int*   batch = (const int*)d_in[2];
    const float* W1    = (const float*)d_in[3];
    const float* b1    = (const float*)d_in[4];
    const float* W2    = (const float*)d_in[5];
    const float* b2    = (const float*)d_in[6];

    int N = in_sizes[2];
    int E = in_sizes[1] / 2;
    int G = out_size / 10;
    if (N > NMAX) N = NMAX;

    int dev = 0;
    cudaGetDevice(&dev);
    int sms = 0;
    cudaDeviceGetAttribute(&sms, cudaDevAttrMultiProcessorCount, dev);
    if (sms < 1) sms = 1;
    int occ = 0;
    cudaOccupancyMaxActiveBlocksPerMultiprocessor(&occ, kAll, 256, 0);
    if (occ < 1) occ = 1;
    int grid = sms * occ;     // guaranteed co-resident -> barrier is deadlock-free

    kAll<<<grid, 256>>>(x, ei, batch, W1, b1, W2, b2, (float*)d_out, N, E, G);
}

// round 17
// speedup vs baseline: 1.2811x; 1.2811x over previous
#include <cuda_runtime.h>
#include <cuda_fp16.h>
#include <cstdint>

#define NMAX 200000
#define GMAX 64

// ---------------- scratch (device-code references ONLY; self-cleaning) --------
__device__ __align__(16) uint4 g_h1h[NMAX];   // 8 x fp16 (6 used): UNscaled x@W1
__device__ __align__(16) uint4 g_u1h[NMAX];   // 8 x fp16: dis*h1 (message)
__device__ __align__(16) uint4 g_a1h[NMAX];   // fp16 accumulator, init = self term
__device__ __align__(16) uint4 g_u2h[NMAX];   // 8 x fp16: dis*relu(layer1)
__device__ __align__(16) uint4 g_a2h[NMAX];   // fp16 accumulator, init = self term
__device__ int      g_deg[NMAX];              // zeroed by kU1 after use
__device__ float    g_dis[NMAX];
__device__ float    g_pool[GMAX * 6];         // zeroed by kPoolOut after use
__device__ float    g_cnt[GMAX];              // zeroed by kPoolOut after use
__device__ unsigned g_ctr;                    // zeroed by kPoolOut after use

// ---------------- helpers ------------------------------------------------------
__device__ __forceinline__ void red2f(float* p, float a, float b) {
    asm volatile("red.global.add.v2.f32 [%0], {%1,%2};"
                 :: "l"(p), "f"(a), "f"(b) : "memory");
}
__device__ __forceinline__ void red16h(uint4* p, uint4 m) {
    asm volatile("red.global.add.noftz.v4.f16x2 [%0], {%1,%2,%3,%4};"
                 :: "l"(p), "r"(m.x), "r"(m.y), "r"(m.z), "r"(m.w) : "memory");
}
__device__ __forceinline__ uint32_t pack2(float a, float b) {
    __half2 h = __floats2half2_rn(a, b);
    return *(uint32_t*)&h;
}
__device__ __forceinline__ float2 up2(uint32_t w) {
    return __half22float2(*(__half2*)&w);
}

// ---------------- K1: fused deg-count + H1 matmul (interleaved roles) -----------
#define H1_NODES 32
__global__ void __launch_bounds__(128) kFused(const float* __restrict__ x,
                                              const int* __restrict__ col,
                                              const float* __restrict__ W1,
                                              int N, int E, int HB, int DB) {
    __shared__ float sx[H1_NODES * 132];
    __shared__ float sW[768];
    int bid = blockIdx.x;
    int mn = (HB < DB) ? HB : DB;
    int T = 2 * mn;
    bool isH1;
    int idx;
    if (bid < T) { isH1 = ((bid & 1) == 0); idx = bid >> 1; }
    else         { idx = mn + (bid - T);    isH1 = (HB > DB); }

    const int tid = threadIdx.x;
    if (!isH1) {
        int base = idx * 1024;
        if (((E & 3) == 0) && base + 1024 <= E) {
            int4 a = *(const int4*)(col + base + tid * 4);
            int4 b = *(const int4*)(col + base + 512 + tid * 4);
            atomicAdd(&g_deg[a.x], 1); atomicAdd(&g_deg[a.y], 1);
            atomicAdd(&g_deg[a.z], 1); atomicAdd(&g_deg[a.w], 1);
            atomicAdd(&g_deg[b.x], 1); atomicAdd(&g_deg[b.y], 1);
            atomicAdd(&g_deg[b.z], 1); atomicAdd(&g_deg[b.w], 1);
        } else {
            for (int e = base + tid; e < E && e < base + 1024; e += 128)
                atomicAdd(&g_deg[__ldg(col + e)], 1);
        }
        return;
    }

    // ---- H1 tile ----
    for (int i = tid; i < 768; i += 128) sW[i] = W1[i];
    const int base = idx * H1_NODES;
#pragma unroll
    for (int it = 0; it < 8; it++) {
        int f = tid + 128 * it;
        int node = f >> 5, c = f & 31;
        int gn = base + node;
        float4 v = make_float4(0.f, 0.f, 0.f, 0.f);
        if (gn < N) v = __ldcs((const float4*)(x + (size_t)gn * 128 + c * 4));
        *(float4*)&sx[node * 132 + c * 4] = v;
    }
    __syncthreads();

    int node = tid >> 2, sub = tid & 3;
    int gn = base + node;
    float a0 = 0.f, a1 = 0.f, a2 = 0.f, a3 = 0.f, a4 = 0.f, a5 = 0.f;
#pragma unroll
    for (int c = sub; c < 32; c += 4) {
        float4 xv = *(const float4*)&sx[node * 132 + c * 4];
        const float4* wp = (const float4*)&sW[c * 24];
        float4 w0 = wp[0], w1 = wp[1], w2 = wp[2], w3 = wp[3], w4 = wp[4], w5 = wp[5];
        a0 += xv.x * w0.x + xv.y * w1.z + xv.z * w3.x + xv.w * w4.z;
        a1 += xv.x * w0.y + xv.y * w1.w + xv.z * w3.y + xv.w * w4.w;
        a2 += xv.x * w0.z + xv.y * w2.x + xv.z * w3.z + xv.w * w5.x;
        a3 += xv.x * w0.w + xv.y * w2.y + xv.z * w3.w + xv.w * w5.y;
        a4 += xv.x * w1.x + xv.y * w2.z + xv.z * w4.x + xv.w * w5.z;
        a5 += xv.x * w1.y + xv.y * w2.w + xv.z * w4.y + xv.w * w5.w;
    }
#pragma unroll
    for (int o = 2; o; o >>= 1) {
        a0 += __shfl_xor_sync(0xffffffffu, a0, o, 4);
        a1 += __shfl_xor_sync(0xffffffffu, a1, o, 4);
        a2 += __shfl_xor_sync(0xffffffffu, a2, o, 4);
        a3 += __shfl_xor_sync(0xffffffffu, a3, o, 4);
        a4 += __shfl_xor_sync(0xffffffffu, a4, o, 4);
        a5 += __shfl_xor_sync(0xffffffffu, a5, o, 4);
    }
    if (sub == 0 && gn < N) {
        uint4 m;
        m.x = pack2(a0, a1);
        m.y = pack2(a2, a3);
        m.z = pack2(a4, a5);
        m.w = 0u;
        g_h1h[gn] = m;
    }
}

// ---------------- K2: dis; u1 = dis*h1; a1 = u1; deg self-clean ------------------
__global__ void kU1(int N) {
    int i = blockIdx.x * blockDim.x + threadIdx.x;
    if (i >= N) return;
    float d = rsqrtf((float)(g_deg[i] + 1));
    g_deg[i] = 0;                              // self-clean for next replay
    g_dis[i] = d;
    uint4 h = g_h1h[i];
    float2 s0 = up2(h.x), s1 = up2(h.y), s2 = up2(h.z);
    uint4 m;
    m.x = pack2(d * s0.x, d * s0.y);
    m.y = pack2(d * s1.x, d * s1.y);
    m.z = pack2(d * s2.x, d * s2.y);
    m.w = 0u;
    g_u1h[i] = m;
    g_a1h[i] = m;
}

// ---------------- K3/K5: edge pass — 8 edges/thread, 2 x int4 idx loads ----------
template<int LAYER>
__global__ void kEdge(const int* __restrict__ ei, int E) {
    int t = (blockIdx.x * blockDim.x + threadIdx.x) * 8;
    if (t >= E) return;
    const uint4* u = (LAYER == 1) ? g_u1h : g_u2h;
    uint4*       a = (LAYER == 1) ? g_a1h : g_a2h;
    if (((E & 7) == 0) && t + 7 < E) {
        int4 r0 = *(const int4*)(ei + t);
        int4 r1 = *(const int4*)(ei + t + 4);
        int4 c0 = *(const int4*)(ei + E + t);
        int4 c1 = *(const int4*)(ei + E + t + 4);
        uint4 m0 = u[r0.x];
        uint4 m1 = u[r0.y];
        uint4 m2 = u[r0.z];
        uint4 m3 = u[r0.w];
        uint4 m4 = u[r1.x];
        uint4 m5 = u[r1.y];
        uint4 m6 = u[r1.z];
        uint4 m7 = u[r1.w];
        red16h(&a[c0.x], m0);
        red16h(&a[c0.y], m1);
        red16h(&a[c0.z], m2);
        red16h(&a[c0.w], m3);
        red16h(&a[c1.x], m4);
        red16h(&a[c1.y], m5);
        red16h(&a[c1.z], m6);
        red16h(&a[c1.w], m7);
    } else {
        for (int e = t; e < E && e < t + 8; e++) {
            int r = __ldg(ei + e), c = __ldg(ei + E + e);
            uint4 m = u[r];
            red16h(&a[c], m);
        }
    }
}

// ---------------- K4: u2 = pack(dis*relu(dis*a1 + b1)); a2 = u2 -------------------
__global__ void kMid(const float* __restrict__ b1, int N) {
    __shared__ float sb[6];
    if (threadIdx.x < 6) sb[threadIdx.x] = b1[threadIdx.x];
    __syncthreads();
    int i = blockIdx.x * blockDim.x + threadIdx.x;
    if (i >= N) return;
    float d = g_dis[i];
    uint4 a = g_a1h[i];
    float2 s0 = up2(a.x), s1 = up2(a.y), s2 = up2(a.z);
    float r0 = fmaxf(d * s0.x + sb[0], 0.f);
    float r1 = fmaxf(d * s0.y + sb[1], 0.f);
    float r2 = fmaxf(d * s1.x + sb[2], 0.f);
    float r3 = fmaxf(d * s1.y + sb[3], 0.f);
    float r4 = fmaxf(d * s2.x + sb[4], 0.f);
    float r5 = fmaxf(d * s2.y + sb[5], 0.f);
    uint4 w;
    w.x = pack2(d * r0, d * r1);
    w.y = pack2(d * r2, d * r3);
    w.z = pack2(d * r4, d * r5);
    w.w = 0u;
    g_u2h[i] = w;
    g_a2h[i] = w;
}

// ---------------- K6: pool + last-block log_softmax + FULL self-clean ------------
__global__ void __launch_bounds__(256) kPoolOut(const int* __restrict__ batch,
                                                const float* __restrict__ W2,
                                                const float* __restrict__ b2,
                                                float* __restrict__ out,
                                                int N, int G, int NB) {
    int i = blockIdx.x * blockDim.x + threadIdx.x;
    float v[6];
    float cn = 0.f;
    int g = -1;
    if (i < N) {
        g = batch[i];
        float d = g_dis[i];
        uint4 a = g_a2h[i];
        float2 s0 = up2(a.x), s1 = up2(a.y), s2 = up2(a.z);
        v[0] = d * s0.x; v[1] = d * s0.y;
        v[2] = d * s1.x; v[3] = d * s1.y;
        v[4] = d * s2.x; v[5] = d * s2.y;
        cn = 1.f;
    } else {
#pragma unroll
        for (int j = 0; j < 6; j++) v[j] = 0.f;
    }
    int g0 = __shfl_sync(0xffffffffu, g, 0);
    bool uni = __all_sync(0xffffffffu, g == g0) && (g0 >= 0);
    if (uni) {
#pragma unroll
        for (int j = 0; j < 6; j++) {
#pragma unroll
            for (int o = 16; o; o >>= 1) v[j] += __shfl_xor_sync(0xffffffffu, v[j], o);
        }
#pragma unroll
        for (int o = 16; o; o >>= 1) cn += __shfl_xor_sync(0xffffffffu, cn, o);
        if ((threadIdx.x & 31) == 0) {
            float* dst = g_pool + g0 * 6;
            red2f(dst,     v[0], v[1]);
            red2f(dst + 2, v[2], v[3]);
            red2f(dst + 4, v[4], v[5]);
            atomicAdd(&g_cnt[g0], cn);
        }
    } else if (g >= 0) {
#pragma unroll
        for (int j = 0; j < 6; j++) atomicAdd(&g_pool[g * 6 + j], v[j]);
        atomicAdd(&g_cnt[g], 1.f);
    }

    // ---- last-block finalization ----
    __threadfence();
    __shared__ bool isLast;
    if (threadIdx.x == 0) {
        unsigned prev = atomicAdd(&g_ctr, 1u);
        isLast = (prev == (unsigned)(NB - 1));
    }
    __syncthreads();
    if (!isLast) return;
    __threadfence();

    __shared__ float sW[60];
    __shared__ float sb[10];
    if (threadIdx.x < 60) sW[threadIdx.x] = W2[threadIdx.x];
    if (threadIdx.x < 10) sb[threadIdx.x] = b2[threadIdx.x];
    __syncthreads();
    int gg = threadIdx.x;
    if (gg < G) {
        float c = fmaxf(g_cnt[gg], 1.f);
        float p[6];
#pragma unroll
        for (int k = 0; k < 6; k++) p[k] = g_pool[gg * 6 + k] / c;
        float vv[10], m = -1e30f;
#pragma unroll
        for (int j = 0; j < 10; j++) {
            float s = sb[j];
#pragma unroll
            for (int k = 0; k < 6; k++) s += p[k] * sW[k * 10 + j];
            vv[j] = s;
            m = fmaxf(m, s);
        }
        float s = 0.f;
#pragma unroll
        for (int j = 0; j < 10; j++) s += expf(vv[j] - m);
        float l = m + logf(s);
#pragma unroll
        for (int j = 0; j < 10; j++) out[gg * 10 + j] = vv[j] - l;
    }
    __syncthreads();
    for (int k = threadIdx.x; k < GMAX * 6; k += 256) g_pool[k] = 0.f;
    if (threadIdx.x < GMAX) g_cnt[threadIdx.x] = 0.f;
    if (threadIdx.x == 0)   g_ctr = 0u;
}

// ---------------- launch -----------------------------------------------------------
extern "C" void kernel_launch(void* const* d_in, const int* in_sizes, int n_in,
                              void* d_out, int out_size) {
    const float* x     = (const float*)d_in[0];
    const int*   ei    = (const int*)d_in[1];
    const int*   batch = (const int*)d_in[2];
    const float* W1    = (const float*)d_in[3];
    const float* b1    = (const float*)d_in[4];
    const float* W2    = (const float*)d_in[5];
    const float* b2    = (const float*)d_in[6];

    int N = in_sizes[2];
    int E = in_sizes[1] / 2;
    int G = out_size / 10;
    if (N > NMAX) N = NMAX;

    int nb  = (N + 255) / 256;
    int eb8 = ((E + 7) / 8 + 255) / 256;
    int HB  = (N + H1_NODES - 1) / H1_NODES;
    int DB  = (E + 1023) / 1024;

    kFused   <<<HB + DB, 128>>>(x, ei + E, W1, N, E, HB, DB);
    kU1      <<<nb, 256>>>(N);
    kEdge<1> <<<eb8, 256>>>(ei, E);
    kMid     <<<nb, 256>>>(b1, N);
    kEdge<2> <<<eb8, 256>>>(ei, E);
    kPoolOut <<<nb, 256>>>(batch, W2, b2, (float*)d_out, N, G, nb);
}